// round 16
// baseline (speedup 1.0000x reference)
#include <cuda_runtime.h>
#include <cstdint>

#define BB 16
#define NN 3000
#define MM 300
#define KK 4
#define LL 80
#define PCAP 128
#define GCAP 32
#define NBLK 144
#define NTHR 1024
#define NGRP 8            // 128-thread groups per block
#define NGID (NBLK * NGRP) // 1152 groups
#define NBUCK (BB * LL)    // 1280 buckets
#define THRESH 0.6f

__device__ __forceinline__ float neg_inf() { return __int_as_float(0xff800000); }

// ---------------- global scratch (zero-init at load; kernel restores) ------
__device__ int g_pcnt[NBUCK];
__device__ int g_gcnt[NBUCK];
__device__ int g_pidx[NBUCK * PCAP];
__device__ int g_gidx[NBUCK * GCAP];
__device__ unsigned g_done;     // scan-arrival counter (target NBLK)
__device__ unsigned g_depart;   // depart counter (target NBLK)

// ---------------- exact-order IoU helpers (no FMA contraction) -------------
struct BoxA { float x0, y0, x1, y1, area; };

__device__ __forceinline__ BoxA cvt_box(float cx, float cy, float w, float h) {
    BoxA r;
    float hw = __fmul_rn(0.5f, w);
    float hh = __fmul_rn(0.5f, h);
    r.x0 = __fsub_rn(cx, hw);
    r.y0 = __fsub_rn(cy, hh);
    r.x1 = __fadd_rn(cx, hw);
    r.y1 = __fadd_rn(cy, hh);
    r.area = __fmul_rn(__fsub_rn(r.x1, r.x0), __fsub_rn(r.y1, r.y0));
    return r;
}

// a = gt box, b = proposal box (union = area_a + area_b - inter, in that order)
__device__ __forceinline__ float iou_ab(const BoxA& a, const BoxA& b) {
    float ltx = fmaxf(a.x0, b.x0);
    float lty = fmaxf(a.y0, b.y0);
    float rbx = fminf(a.x1, b.x1);
    float rby = fminf(a.y1, b.y1);
    float wx = fmaxf(__fsub_rn(rbx, ltx), 0.0f);
    float wy = fmaxf(__fsub_rn(rby, lty), 0.0f);
    float inter = __fmul_rn(wx, wy);
    float uni = __fsub_rn(__fadd_rn(a.area, b.area), inter);
    return __fdiv_rn(inter, fmaxf(uni, 1e-9f));
}

// total order: (value desc, index asc) — order-independent, tie-safe
__device__ __forceinline__ bool cmpvi(float v, int i, float w, int j) {
    return (v > w) || (v == w && i < j);
}

// group-scoped named barrier (ids 1..8; 128 threads each, warp-aligned)
#define GBAR(g) asm volatile("bar.sync %0, %1;" :: "r"((g) + 1), "r"(128) : "memory")

// ---------------- per-group smem (~21.5KB; x8 = ~172KB -> 1 block/SM) ------
struct SmemGroup {
    float spx0[PCAP], spy0[PCAP], spx1[PCAP], spy1[PCAP], spar[PCAP];
    int   spn[PCAP];
    float sgx0[GCAP], sgy0[GCAP], sgx1[GCAP], sgy1[GCAP], sgar[GCAP], sgmx[GCAP];
    int   sgm[GCAP];
    int   scnt[GCAP];
    float stv[GCAP * KK];
    int   sti[GCAP * KK];
    float siou[GCAP * PCAP];
    int   s_pc, s_gc;
};

// ---------------- fused kernel: scan -> grid barrier -> group buckets -------
__global__ void __launch_bounds__(NTHR, 1)
kAll(const float* __restrict__ props,     // (B,N,4) cxcywh
     const int4*  __restrict__ pinds4,    // (B,N) as int4
     const int4*  __restrict__ gtl4,      // (B,M) as int4
     const float* __restrict__ gtb,       // (B,M,4) cxcywh
     float* __restrict__ out) {
    extern __shared__ char raw[];
    const int t = threadIdx.x;
    const int g = t >> 7;                 // group 0..7
    const int tl = t & 127;               // thread within group
    SmemGroup* s = reinterpret_cast<SmemGroup*>(raw) + g;

    // ================= scan phase: 1/NBLK slice per block ===================
    {
        int i = blockIdx.x * NTHR + t;
        if (i < BB * NN / 4) {
            int b = i / (NN / 4);
            int n0 = (i % (NN / 4)) * 4;
            int4 v = pinds4[i];
            int labs[4] = {v.x, v.y, v.z, v.w};
#pragma unroll
            for (int q = 0; q < 4; q++) {
                int lab = labs[q];
                if ((unsigned)lab < LL) {
                    int bk = b * LL + lab;
                    int slot = atomicAdd(&g_pcnt[bk], 1);
                    if (slot < PCAP) g_pidx[bk * PCAP + slot] = n0 + q;
                }
            }
            __threadfence();
        } else if (i < BB * NN / 4 + BB * MM / 4) {
            int j = i - BB * NN / 4;
            int b = j / (MM / 4);
            int m0 = (j % (MM / 4)) * 4;
            int4 v = gtl4[j];
            int labs[4] = {v.x, v.y, v.z, v.w};
#pragma unroll
            for (int q = 0; q < 4; q++) {
                int lab = labs[q];
                if ((unsigned)lab < LL) {
                    int bk = b * LL + lab;
                    int slot = atomicAdd(&g_gcnt[bk], 1);
                    if (slot < GCAP) g_gidx[bk * GCAP + slot] = m0 + q;
                }
            }
            __threadfence();
        }
    }
    __syncthreads();

    // ============ grid barrier: all NBLK blocks are wave-1 resident =========
    if (t == 0) {
        atomicAdd(&g_done, 1u);
        while (*(volatile unsigned*)&g_done < (unsigned)NBLK) __nanosleep(128);
        __threadfence();                  // acquire
    }
    __syncthreads();

    // ================= bucket phase: groups independent =====================
#pragma unroll 1
    for (int r = 0; r < 2; r++) {
        const int bk = r * NGID + g * NBLK + blockIdx.x;
        if (bk >= NBUCK) continue;        // uniform across group
        const int b = bk / LL;

        if (tl == 0) {
            s->s_pc = g_pcnt[bk];
            s->s_gc = g_gcnt[bk];
            g_pcnt[bk] = 0;               // restore zero-invariant (per bucket, once)
            g_gcnt[bk] = 0;
        }
        if (tl < GCAP) s->scnt[tl] = 0;
        GBAR(g);

        const int gc = min(s->s_gc, GCAP);
        if (gc == 0) continue;            // counters already reset
        const int pc = min(s->s_pc, PCAP);

        // ---- gather + convert live bucket members into group smem ----
        if (tl < pc) {
            int n = g_pidx[bk * PCAP + tl];
            float4 p4 = reinterpret_cast<const float4*>(props)[(size_t)b * NN + n];
            BoxA p = cvt_box(p4.x, p4.y, p4.z, p4.w);
            s->spx0[tl] = p.x0; s->spy0[tl] = p.y0; s->spx1[tl] = p.x1; s->spy1[tl] = p.y1;
            s->spar[tl] = p.area; s->spn[tl] = n;
        }
        if (tl < gc) {
            int m = g_gidx[bk * GCAP + tl];
            float4 g4 = reinterpret_cast<const float4*>(gtb)[(size_t)b * MM + m];
            BoxA gg = cvt_box(g4.x, g4.y, g4.z, g4.w);
            s->sgx0[tl] = gg.x0; s->sgy0[tl] = gg.y0; s->sgx1[tl] = gg.x1; s->sgy1[tl] = gg.y1;
            s->sgar[tl] = gg.area; s->sgm[tl] = m;
        }
        GBAR(g);

        // ---- phase A: warp per GT -> IoU row (stored) + redux top-4 ----
        {
            const int warp = tl >> 5, lane = tl & 31;
            for (int j = warp; j < gc; j += 4) {
                BoxA gg;
                gg.x0 = s->sgx0[j]; gg.y0 = s->sgy0[j]; gg.x1 = s->sgx1[j]; gg.y1 = s->sgy1[j];
                gg.area = s->sgar[j];

                float av0 = neg_inf(), av1 = neg_inf(), av2 = neg_inf(), av3 = neg_inf();
                int   an0 = 0x7fffffff, an1 = 0x7fffffff, an2 = 0x7fffffff, an3 = 0x7fffffff;
                for (int i = lane; i < pc; i += 32) {
                    BoxA p;
                    p.x0 = s->spx0[i]; p.y0 = s->spy0[i]; p.x1 = s->spx1[i]; p.y1 = s->spy1[i];
                    p.area = s->spar[i];
                    int n = s->spn[i];
                    float v = iou_ab(gg, p);
                    s->siou[j * PCAP + i] = v;       // matrix row (conflict-free)
                    if (cmpvi(v, n, av3, an3)) {
                        if (cmpvi(v, n, av0, an0)) {
                            av3 = av2; an3 = an2; av2 = av1; an2 = an1; av1 = av0; an1 = an0;
                            av0 = v; an0 = n;
                        } else if (cmpvi(v, n, av1, an1)) {
                            av3 = av2; an3 = an2; av2 = av1; an2 = an1;
                            av1 = v; an1 = n;
                        } else if (cmpvi(v, n, av2, an2)) {
                            av3 = av2; an3 = an2;
                            av2 = v; an2 = n;
                        } else {
                            av3 = v; an3 = n;
                        }
                    }
                }

                // 4 extraction rounds via redux.sync (key: IoU>=0 -> bits|msb)
#pragma unroll
                for (int rr = 0; rr < 4; rr++) {
                    unsigned key = (av0 >= 0.0f) ? (__float_as_uint(av0) | 0x80000000u) : 0u;
                    unsigned kmax = __reduce_max_sync(0xffffffffu, key);
                    unsigned nmin = __reduce_min_sync(0xffffffffu,
                                        (key == kmax) ? (unsigned)an0 : 0xffffffffu);
                    float wv; int wn;
                    if (kmax != 0u) { wv = __uint_as_float(kmax & 0x7fffffffu); wn = (int)nmin; }
                    else            { wv = -1.0f; wn = 0; }
                    if (lane == rr) { s->stv[j * KK + rr] = wv; s->sti[j * KK + rr] = wn; }
                    if (rr == 0 && lane == 0) s->sgmx[j] = wv;   // row max (exact bits)
                    if (key == kmax && (unsigned)an0 == nmin) {
                        av0 = av1; an0 = an1; av1 = av2; an1 = an2;
                        av2 = av3; an2 = an3; av3 = neg_inf(); an3 = 0x7fffffff;
                    }
                }
            }
        }
        GBAR(g);

        // ---- phase B: thread per proposal; pure smem reads ----
        if (tl < pc) {
            float bestv = neg_inf();
            int bestm = 0x7fffffff, bestj = 0;
            bool lq = false;
            for (int j = 0; j < gc; j++) {
                float v = s->siou[j * PCAP + tl];    // exact bits from phase A
                if (v == s->sgmx[j]) lq = true;
                int m = s->sgm[j];
                if (v > bestv || (v == bestv && m < bestm)) { bestv = v; bestm = m; bestj = j; }
            }
            if (bestv >= THRESH || lq)
                atomicAdd(&s->scnt[bestj], 1);
        }
        GBAR(g);

        // ---- phase C: thread j writes GT j's 16 output floats ----
        if (tl < gc) {
            const int m = s->sgm[tl];
            const int bm = b * MM + m;
            int take = s->scnt[tl];
            take = take < KK ? take : KK;
            const int S = BB * MM * KK;
#pragma unroll
            for (int q = 0; q < KK; q++) {
                bool val = q < take;
                out[bm * KK + q]         = val ? (float)s->sti[tl * KK + q] : -1.0f;
                out[S + bm * KK + q]     = val ? (float)m : -1.0f;
                out[2 * S + bm * KK + q] = val ? 1.0f : 0.0f;
                out[3 * S + bm * KK + q] = val ? s->stv[tl * KK + q] : 0.0f;
            }
        }
        GBAR(g);   // protect smem reuse in next round
    }

    // ============ depart + reset (every block, exactly once) ================
    __syncthreads();
    if (t == 0) {
        unsigned d = atomicAdd(&g_depart, 1u);
        if (d == (unsigned)NBLK - 1u) {   // last block out resets flags
            g_done = 0;
            g_depart = 0;
        }
    }
}

// ---------------- launch ----------------------------------------------------
extern "C" void kernel_launch(void* const* d_in, const int* in_sizes, int n_in,
                              void* d_out, int out_size) {
    // metadata order: pred_logits_match, pred_boxes, init_reference,
    //                 prompt_inds, gt_labels, gt_boxes, max_k
    const float* props = (const float*)d_in[2];   // init_reference (B,N,4)
    const int*   pinds = (const int*)d_in[3];     // prompt_inds    (B,N)
    const int*   gtl   = (const int*)d_in[4];     // gt_labels      (B,M)
    const float* gtb   = (const float*)d_in[5];   // gt_boxes       (B,M,4)

    const int smem = (int)(sizeof(SmemGroup) * NGRP);
    cudaFuncSetAttribute(kAll, cudaFuncAttributeMaxDynamicSharedMemorySize, smem);
    kAll<<<NBLK, NTHR, smem>>>(props, (const int4*)pinds, (const int4*)gtl,
                               gtb, (float*)d_out);
}

// round 17
// speedup vs baseline: 1.9734x; 1.9734x over previous
#include <cuda_runtime.h>
#include <cstdint>

#define BB 16
#define NN 3000
#define MM 300
#define KK 4
#define LL 80
#define PCAP 128
#define GCAP 32
#define THRESH 0.6f

__device__ __forceinline__ float neg_inf() { return __int_as_float(0xff800000); }

// ---------------- global bucket scratch (zero-init at load; kMain restores) -
__device__ int    g_pcnt[BB * LL];
__device__ int    g_gcnt[BB * LL];
__device__ float4 g_p1[BB * LL * PCAP];   // proposal (x0,y0,x1,y1) converted
__device__ float2 g_p2[BB * LL * PCAP];   // proposal (area, n_as_bits)
__device__ float4 g_g1[BB * LL * GCAP];   // gt (x0,y0,x1,y1) converted
__device__ float2 g_g2[BB * LL * GCAP];   // gt (area, m_as_bits)

// ---------------- exact-order IoU helpers (no FMA contraction) -------------
struct BoxA { float x0, y0, x1, y1, area; };

__device__ __forceinline__ BoxA cvt_box(float cx, float cy, float w, float h) {
    BoxA r;
    float hw = __fmul_rn(0.5f, w);
    float hh = __fmul_rn(0.5f, h);
    r.x0 = __fsub_rn(cx, hw);
    r.y0 = __fsub_rn(cy, hh);
    r.x1 = __fadd_rn(cx, hw);
    r.y1 = __fadd_rn(cy, hh);
    r.area = __fmul_rn(__fsub_rn(r.x1, r.x0), __fsub_rn(r.y1, r.y0));
    return r;
}

// a = gt box, b = proposal box (union = area_a + area_b - inter, in that order)
__device__ __forceinline__ float iou_ab(const BoxA& a, const BoxA& b) {
    float ltx = fmaxf(a.x0, b.x0);
    float lty = fmaxf(a.y0, b.y0);
    float rbx = fminf(a.x1, b.x1);
    float rby = fminf(a.y1, b.y1);
    float wx = fmaxf(__fsub_rn(rbx, ltx), 0.0f);
    float wy = fmaxf(__fsub_rn(rby, lty), 0.0f);
    float inter = __fmul_rn(wx, wy);
    float uni = __fsub_rn(__fadd_rn(a.area, b.area), inter);
    return __fdiv_rn(inter, fmaxf(uni, 1e-9f));
}

// total order: (value desc, index asc) — order-independent, tie-safe
__device__ __forceinline__ bool cmpvi(float v, int i, float w, int j) {
    return (v > w) || (v == w && i < j);
}

// group-scoped named barrier (ids 1..2; 128 threads, warp-aligned)
#define GBAR(g) asm volatile("bar.sync %0, %1;" :: "r"((g) + 1), "r"(128) : "memory")

// ---------------- kernel S: vectorized scan -> converted record scatter -----
__global__ void __launch_bounds__(128) kS(const float* __restrict__ props,
                                          const int4* __restrict__ pinds4,
                                          const float* __restrict__ gtb,
                                          const int4* __restrict__ gtl4) {
    int i = blockIdx.x * 128 + threadIdx.x;
    if (i < BB * NN / 4) {
        int b = i / (NN / 4);
        int n0 = (i % (NN / 4)) * 4;
        int4 v = pinds4[i];
        int labs[4] = {v.x, v.y, v.z, v.w};
#pragma unroll
        for (int q = 0; q < 4; q++) {
            int lab = labs[q];
            if ((unsigned)lab < LL) {
                int bk = b * LL + lab;
                int slot = atomicAdd(&g_pcnt[bk], 1);
                if (slot < PCAP) {
                    int n = n0 + q;
                    float4 p4 = reinterpret_cast<const float4*>(props)[(size_t)b * NN + n];
                    BoxA p = cvt_box(p4.x, p4.y, p4.z, p4.w);
                    size_t idx = (size_t)bk * PCAP + slot;
                    g_p1[idx] = make_float4(p.x0, p.y0, p.x1, p.y1);
                    g_p2[idx] = make_float2(p.area, __int_as_float(n));
                }
            }
        }
    } else if (i < BB * NN / 4 + BB * MM / 4) {
        int j = i - BB * NN / 4;
        int b = j / (MM / 4);
        int m0 = (j % (MM / 4)) * 4;
        int4 v = gtl4[j];
        int labs[4] = {v.x, v.y, v.z, v.w};
#pragma unroll
        for (int q = 0; q < 4; q++) {
            int lab = labs[q];
            if ((unsigned)lab < LL) {
                int bk = b * LL + lab;
                int slot = atomicAdd(&g_gcnt[bk], 1);
                if (slot < GCAP) {
                    int m = m0 + q;
                    float4 g4 = reinterpret_cast<const float4*>(gtb)[(size_t)b * MM + m];
                    BoxA g = cvt_box(g4.x, g4.y, g4.z, g4.w);
                    size_t idx = (size_t)bk * GCAP + slot;
                    g_g1[idx] = make_float4(g.x0, g.y0, g.x1, g.y1);
                    g_g2[idx] = make_float2(g.area, __int_as_float(m));
                }
            }
        }
    }
}

// ---------------- per-group smem (~21.5KB; x2 = ~43KB -> 5 blocks/SM) ------
struct SmemGroup {
    float spx0[PCAP], spy0[PCAP], spx1[PCAP], spy1[PCAP], spar[PCAP];
    int   spn[PCAP];
    float sgx0[GCAP], sgy0[GCAP], sgx1[GCAP], sgy1[GCAP], sgar[GCAP], sgmx[GCAP];
    int   sgm[GCAP];
    int   scnt[GCAP];
    float stv[GCAP * KK];
    int   sti[GCAP * KK];
    float siou[GCAP * PCAP];
    int   s_pc, s_gc;
};

// ---------------- kernel M: 2 independent bucket-groups per block -----------
__global__ void __launch_bounds__(256)
kMain(float* __restrict__ out) {
    __shared__ SmemGroup sg[2];

    const int t  = threadIdx.x;
    const int g  = t >> 7;               // group 0..1
    const int tl = t & 127;              // thread within group
    const int bk = blockIdx.x * 2 + g;   // bucket = b * LL + lab
    const int b  = bk / LL;
    SmemGroup* s = &sg[g];

    // ---- single-hop record loads (all independent; stale slots never consumed) ----
    float4 q1 = g_p1[(size_t)bk * PCAP + tl];
    float2 q2 = g_p2[(size_t)bk * PCAP + tl];
    if (tl == 0) {
        s->s_pc = g_pcnt[bk];
        s->s_gc = g_gcnt[bk];
        g_pcnt[bk] = 0;                  // restore zero-invariant for graph replay
        g_gcnt[bk] = 0;
    }
    if (tl < GCAP) s->scnt[tl] = 0;

    s->spx0[tl] = q1.x; s->spy0[tl] = q1.y; s->spx1[tl] = q1.z; s->spy1[tl] = q1.w;
    s->spar[tl] = q2.x; s->spn[tl] = __float_as_int(q2.y);

    if (tl < GCAP) {
        float4 r1 = g_g1[(size_t)bk * GCAP + tl];
        float2 r2 = g_g2[(size_t)bk * GCAP + tl];
        s->sgx0[tl] = r1.x; s->sgy0[tl] = r1.y; s->sgx1[tl] = r1.z; s->sgy1[tl] = r1.w;
        s->sgar[tl] = r2.x; s->sgm[tl] = __float_as_int(r2.y);
    }
    GBAR(g);

    const int gc = min(s->s_gc, GCAP);
    if (gc == 0) return;                 // group owns no GT rows (no later group bars)
    const int pc = min(s->s_pc, PCAP);

    // ---- phase A: warp per GT -> IoU row (stored) + redux top-4 extraction ----
    {
        const int warp = tl >> 5, lane = tl & 31;
        for (int j = warp; j < gc; j += 4) {
            BoxA gg;
            gg.x0 = s->sgx0[j]; gg.y0 = s->sgy0[j]; gg.x1 = s->sgx1[j]; gg.y1 = s->sgy1[j];
            gg.area = s->sgar[j];

            // per-lane sorted-4 candidates (<=4 items since pc<=128)
            float av0 = neg_inf(), av1 = neg_inf(), av2 = neg_inf(), av3 = neg_inf();
            int   an0 = 0x7fffffff, an1 = 0x7fffffff, an2 = 0x7fffffff, an3 = 0x7fffffff;
            for (int i = lane; i < pc; i += 32) {
                BoxA p;
                p.x0 = s->spx0[i]; p.y0 = s->spy0[i]; p.x1 = s->spx1[i]; p.y1 = s->spy1[i];
                p.area = s->spar[i];
                int n = s->spn[i];
                float v = iou_ab(gg, p);
                s->siou[j * PCAP + i] = v;           // matrix row (conflict-free)
                if (cmpvi(v, n, av3, an3)) {
                    if (cmpvi(v, n, av0, an0)) {
                        av3 = av2; an3 = an2; av2 = av1; an2 = an1; av1 = av0; an1 = an0;
                        av0 = v; an0 = n;
                    } else if (cmpvi(v, n, av1, an1)) {
                        av3 = av2; an3 = an2; av2 = av1; an2 = an1;
                        av1 = v; an1 = n;
                    } else if (cmpvi(v, n, av2, an2)) {
                        av3 = av2; an3 = an2;
                        av2 = v; an2 = n;
                    } else {
                        av3 = v; an3 = n;
                    }
                }
            }

            // 4 extraction rounds via redux.sync (key: IoU>=0 -> bits|msb; sentinel 0)
#pragma unroll
            for (int r = 0; r < 4; r++) {
                unsigned key = (av0 >= 0.0f) ? (__float_as_uint(av0) | 0x80000000u) : 0u;
                unsigned kmax = __reduce_max_sync(0xffffffffu, key);
                unsigned nmin = __reduce_min_sync(0xffffffffu,
                                    (key == kmax) ? (unsigned)an0 : 0xffffffffu);
                float wv; int wn;
                if (kmax != 0u) { wv = __uint_as_float(kmax & 0x7fffffffu); wn = (int)nmin; }
                else            { wv = -1.0f; wn = 0; }
                if (lane == r) { s->stv[j * KK + r] = wv; s->sti[j * KK + r] = wn; }
                if (r == 0 && lane == 0) s->sgmx[j] = wv;    // row max (exact bits)
                // winner advances its candidate shift-register
                if (key == kmax && (unsigned)an0 == nmin) {
                    av0 = av1; an0 = an1; av1 = av2; an1 = an2;
                    av2 = av3; an2 = an3; av3 = neg_inf(); an3 = 0x7fffffff;
                }
            }
        }
    }
    GBAR(g);

    // ---- phase B: thread i = proposal i; pure smem reads (no IoU recompute) ----
    if (tl < pc) {
        float bestv = neg_inf();
        int bestm = 0x7fffffff, bestj = 0;
        bool lq = false;
        for (int j = 0; j < gc; j++) {
            float v = s->siou[j * PCAP + tl];        // exact bits from phase A
            if (v == s->sgmx[j]) lq = true;
            int m = s->sgm[j];
            if (v > bestv || (v == bestv && m < bestm)) { bestv = v; bestm = m; bestj = j; }
        }
        // matching IoU >= 0 beats all non-matching NEG entries -> bestm == ref best_gt
        if (bestv >= THRESH || lq)
            atomicAdd(&s->scnt[bestj], 1);
    }
    GBAR(g);

    // ---- phase C: thread j writes GT j's 16 output floats ----
    if (tl < gc) {
        const int m = s->sgm[tl];
        const int bm = b * MM + m;
        int take = s->scnt[tl];
        take = take < KK ? take : KK;
        const int S = BB * MM * KK;
#pragma unroll
        for (int q = 0; q < KK; q++) {
            bool val = q < take;
            out[bm * KK + q]         = val ? (float)s->sti[tl * KK + q] : -1.0f;
            out[S + bm * KK + q]     = val ? (float)m : -1.0f;
            out[2 * S + bm * KK + q] = val ? 1.0f : 0.0f;
            out[3 * S + bm * KK + q] = val ? s->stv[tl * KK + q] : 0.0f;
        }
    }
}

// ---------------- launch ----------------------------------------------------
extern "C" void kernel_launch(void* const* d_in, const int* in_sizes, int n_in,
                              void* d_out, int out_size) {
    // metadata order: pred_logits_match, pred_boxes, init_reference,
    //                 prompt_inds, gt_labels, gt_boxes, max_k
    const float* props = (const float*)d_in[2];   // init_reference (B,N,4)
    const int*   pinds = (const int*)d_in[3];     // prompt_inds    (B,N)
    const int*   gtl   = (const int*)d_in[4];     // gt_labels      (B,M)
    const float* gtb   = (const float*)d_in[5];   // gt_boxes       (B,M,4)

    const int nscan = BB * NN / 4 + BB * MM / 4;  // 13200
    kS<<<(nscan + 127) / 128, 128>>>(props, (const int4*)pinds,
                                     gtb, (const int4*)gtl);
    kMain<<<BB * LL / 2, 256>>>((float*)d_out);
}